// round 15
// baseline (speedup 1.0000x reference)
#include <cuda_runtime.h>
#include <cuda_fp16.h>
#include <cstdint>

#define NN 100000
#define EE 1600000
#define RR 8
#define DD 128
#define M8 (NN * RR)       // sort bins, key = dst*8 + rel

// ---------------------------------------------------------------------------
// Scratch (device globals; no allocation allowed anywhere).
// ---------------------------------------------------------------------------
__device__ __align__(16) __half g_x16[(size_t)NN * DD];        // fp16 features (layer in)
__device__ __align__(16) __half g_h16[(size_t)NN * DD];        // fp16 hidden
__device__ __align__(16) __half g_xbar[(size_t)NN * RR * DD];  // per-(dst,rel) means
__device__ __align__(16) __half g_w16[9 * DD * DD];  // [mat][n][k] weights fp16
__device__ int g_cnt[M8];
__device__ int g_off[M8];
__device__ int g_cur[M8];
__device__ int g_bsum[1024];
__device__ int g_pack[EE];     // src ids, sorted by (dst,rel)
__device__ int g_shift;        // 1 if edge arrays are int64, 0 if int32

// ---------------------------------------------------------------------------
// dtype autodetect (int64 edges => all odd 32-bit words zero)
// ---------------------------------------------------------------------------
__global__ void detect_k(const int* __restrict__ et, int E) {
    __shared__ int any;
    if (threadIdx.x == 0) any = 0;
    __syncthreads();
    int n = min(E, 4096);
    int local = 0;
    for (int i = threadIdx.x; i < n; i += blockDim.x) local |= et[2 * i + 1];
    if (local) atomicOr(&any, 1);
    __syncthreads();
    if (threadIdx.x == 0) g_shift = any ? 0 : 1;
}

// ---------------------------------------------------------------------------
// Counting sort by key (dst*8 + rel)
// ---------------------------------------------------------------------------
__global__ void zero_cnt_k(int* __restrict__ c) {
    int i = blockIdx.x * blockDim.x + threadIdx.x;
    if (i < M8) c[i] = 0;
}
__global__ void count_k(const int* __restrict__ ei, const int* __restrict__ et,
                        int* __restrict__ cnt, int E) {
    int e = blockIdx.x * blockDim.x + threadIdx.x;
    if (e < E) {
        const int sh = g_shift;
        int d = ei[(E << sh) + (e << sh)];
        int r = et[e << sh];
        if ((unsigned)d < NN && (unsigned)r < RR)
            atomicAdd(&cnt[d * RR + r], 1);
    }
}
__global__ void scan1_k(const int* __restrict__ cnt, int* __restrict__ off,
                        int* __restrict__ bsum, int M) {
    __shared__ int wsum[8];
    const int t = threadIdx.x;
    const int base = blockIdx.x * 1024 + t * 4;
    int v0 = 0, v1 = 0, v2 = 0, v3 = 0;
    if (base + 0 < M) v0 = cnt[base + 0];
    if (base + 1 < M) v1 = cnt[base + 1];
    if (base + 2 < M) v2 = cnt[base + 2];
    if (base + 3 < M) v3 = cnt[base + 3];
    const int tsum = v0 + v1 + v2 + v3;
    const int lane = t & 31, wid = t >> 5;
    int x = tsum;
#pragma unroll
    for (int o = 1; o < 32; o <<= 1) {
        int y = __shfl_up_sync(~0u, x, o);
        if (lane >= o) x += y;
    }
    if (lane == 31) wsum[wid] = x;
    __syncthreads();
    if (wid == 0) {
        int w = (lane < 8) ? wsum[lane] : 0;
#pragma unroll
        for (int o = 1; o < 8; o <<= 1) {
            int y = __shfl_up_sync(~0u, w, o);
            if (lane >= o) w += y;
        }
        if (lane < 8) wsum[lane] = w;
    }
    __syncthreads();
    const int excl = x - tsum + (wid > 0 ? wsum[wid - 1] : 0);
    if (base + 0 < M) off[base + 0] = excl;
    if (base + 1 < M) off[base + 1] = excl + v0;
    if (base + 2 < M) off[base + 2] = excl + v0 + v1;
    if (base + 3 < M) off[base + 3] = excl + v0 + v1 + v2;
    if (t == 0) bsum[blockIdx.x] = wsum[7];
}
__global__ void scan2_k(int* __restrict__ bsum, int nb) {
    __shared__ int sh[1024];
    const int t = threadIdx.x;
    sh[t] = (t < nb) ? bsum[t] : 0;
    __syncthreads();
    for (int o = 1; o < 1024; o <<= 1) {
        int v = (t >= o) ? sh[t - o] : 0;
        __syncthreads();
        sh[t] += v;
        __syncthreads();
    }
    if (t < nb) bsum[t] = (t == 0) ? 0 : sh[t - 1];
}
__global__ void scan3_k(int* __restrict__ off, int* __restrict__ cur,
                        const int* __restrict__ bsum, int M) {
    int i = blockIdx.x * blockDim.x + threadIdx.x;
    if (i < M) {
        int v = off[i] + bsum[i >> 10];
        off[i] = v;
        cur[i] = v;
    }
}
__global__ void scatter_k(const int* __restrict__ ei, const int* __restrict__ et,
                          int* __restrict__ cur, int* __restrict__ pack, int E) {
    int e = blockIdx.x * blockDim.x + threadIdx.x;
    if (e < E) {
        const int sh = g_shift;
        int s = ei[e << sh];
        int d = ei[(E << sh) + (e << sh)];
        int r = et[e << sh];
        if ((unsigned)d < NN && (unsigned)r < RR && (unsigned)s < NN) {
            int pos = atomicAdd(&cur[d * RR + r], 1);
            pack[pos] = s;
        }
    }
}

// ---------------------------------------------------------------------------
// fp32 -> fp16 feature conversion
// ---------------------------------------------------------------------------
__global__ void cvt16_k(const float* __restrict__ A, __half* __restrict__ B, size_t n4) {
    size_t i = (size_t)blockIdx.x * blockDim.x + threadIdx.x;
    if (i < n4) {
        float4 v = ((const float4*)A)[i];
        __half2 a = __float22half2_rn(make_float2(v.x, v.y));
        __half2 b = __float22half2_rn(make_float2(v.z, v.w));
        ((__half2*)B)[2 * i]     = a;
        ((__half2*)B)[2 * i + 1] = b;
    }
}

// ---------------------------------------------------------------------------
// Weight transpose to fp16: out[mat][n][k]; mat0=root, 1..8=W[r]
// ---------------------------------------------------------------------------
__global__ void cvtw9_k(const float* __restrict__ root, const float* __restrict__ W,
                        __half* __restrict__ H) {
    int idx = blockIdx.x * blockDim.x + threadIdx.x;
    if (idx < 9 * DD * DD) {
        int mat = idx >> 14;
        int rem = idx & 16383;
        int n = rem >> 7;
        int k = rem & 127;
        float v = (mat == 0) ? root[(k << 7) + n] : W[((mat - 1) << 14) + (k << 7) + n];
        H[idx] = __float2half_rn(v);
    }
}

// ---------------------------------------------------------------------------
// Gather-mean: xbar[d][r] = mean over edges (sorted (dst,rel)) of src16[src].
// One warp per dst. FLAT loop over the dst's whole edge range (all 8 bins),
// 4-way unrolled -> 4 independent L2 gathers in flight regardless of tiny
// per-bin sizes. Edge relation recovered from boundary registers; adds go to
// 8 register accumulators via compile-time predication (per-bin add order
// preserved -> bit-identical results).
// ---------------------------------------------------------------------------
__global__ void aggx_k(const int* __restrict__ off, const int* __restrict__ pack,
                       const __half* __restrict__ src16, __half* __restrict__ xbar,
                       int E) {
    const int d = (blockIdx.x * blockDim.x + threadIdx.x) >> 5;
    if (d >= NN) return;
    const int lane = threadIdx.x & 31;
    const int base = d * RR;

    int v = E;
    if (lane < 9 && base + lane < M8) v = off[base + lane];

    // Broadcast all 9 boundaries to every lane.
    int b[9];
#pragma unroll
    for (int r = 0; r < 9; r++) b[r] = __shfl_sync(~0u, v, r);
    const int lo = b[0], hi = b[8];

    const int c4 = lane * 4;
    float4 acc[RR];
#pragma unroll
    for (int r = 0; r < RR; r++) acc[r] = make_float4(0.f, 0.f, 0.f, 0.f);

    for (int i = lo; i < hi; i += 4) {
        const int n = hi - i;               // >=1
        // Independent index loads (clamped; lanes uniform so no divergence)
        const int i1 = (n > 1) ? i + 1 : i;
        const int i2 = (n > 2) ? i + 2 : i;
        const int i3 = (n > 3) ? i + 3 : i;
        const int s0 = pack[i],  s1 = pack[i1];
        const int s2 = pack[i2], s3 = pack[i3];
        // Independent gathers (MLP = 4)
        const float2 q0 = *(const float2*)(src16 + (size_t)s0 * DD + c4);
        const float2 q1 = *(const float2*)(src16 + (size_t)s1 * DD + c4);
        const float2 q2 = *(const float2*)(src16 + (size_t)s2 * DD + c4);
        const float2 q3 = *(const float2*)(src16 + (size_t)s3 * DD + c4);
        float4 f0, f1, f2, f3;
        {
            float2 a, bq;
            a = __half22float2(*(const __half2*)&q0.x); bq = __half22float2(*(const __half2*)&q0.y);
            f0 = make_float4(a.x, a.y, bq.x, bq.y);
            a = __half22float2(*(const __half2*)&q1.x); bq = __half22float2(*(const __half2*)&q1.y);
            f1 = make_float4(a.x, a.y, bq.x, bq.y);
            a = __half22float2(*(const __half2*)&q2.x); bq = __half22float2(*(const __half2*)&q2.y);
            f2 = make_float4(a.x, a.y, bq.x, bq.y);
            a = __half22float2(*(const __half2*)&q3.x); bq = __half22float2(*(const __half2*)&q3.y);
            f3 = make_float4(a.x, a.y, bq.x, bq.y);
        }
        // Relation of each edge: count boundaries passed.
        int r0 = 0, r1 = 0, r2 = 0, r3 = 0;
#pragma unroll
        for (int r = 1; r < RR; r++) {
            r0 += (i      >= b[r]);
            r1 += (i + 1  >= b[r]);
            r2 += (i + 2  >= b[r]);
            r3 += (i + 3  >= b[r]);
        }
        // Predicated accumulate (in-order within each bin).
#pragma unroll
        for (int r = 0; r < RR; r++) {
            if (r0 == r)          { acc[r].x += f0.x; acc[r].y += f0.y; acc[r].z += f0.z; acc[r].w += f0.w; }
            if (n > 1 && r1 == r) { acc[r].x += f1.x; acc[r].y += f1.y; acc[r].z += f1.z; acc[r].w += f1.w; }
            if (n > 2 && r2 == r) { acc[r].x += f2.x; acc[r].y += f2.y; acc[r].z += f2.z; acc[r].w += f2.w; }
            if (n > 3 && r3 == r) { acc[r].x += f3.x; acc[r].y += f3.y; acc[r].z += f3.z; acc[r].w += f3.w; }
        }
    }

    // Write means.
#pragma unroll
    for (int r = 0; r < RR; r++) {
        const int cntr = b[r + 1] - b[r];
        const float inv = (cntr > 0) ? (1.0f / (float)cntr) : 0.f;
        __half2 o0 = __float22half2_rn(make_float2(acc[r].x * inv, acc[r].y * inv));
        __half2 o1 = __float22half2_rn(make_float2(acc[r].z * inv, acc[r].w * inv));
        float2 ov;
        *(__half2*)&ov.x = o0;
        *(__half2*)&ov.y = o1;
        *(float2*)(xbar + ((size_t)base + r) * DD + c4) = ov;
    }
}

// ---------------------------------------------------------------------------
// K=1152 GEMM: out = act( concat(x16, xbar_0..7)[M,1152] @ Wcat[1152,128] + b )
// 256 threads (8 warps, 4m x 2n), tile M=128 x N=128, 2 CTAs/SM.
// 18 k-half chunks (9 mats x 2 halves of 64) through a 3-stage cp.async ring.
// Single fp16 MMA pass; fp32 accumulate; fused bias/relu epilogue.
// ---------------------------------------------------------------------------
#define TM 128
#define NTHR 256
#define CH 72                            // chunk row stride (64 data + 8 pad)
#define A_ST (TM * CH * 2)               // 18432
#define B_ST (128 * CH * 2)              // 18432
#define STAGE (A_ST + B_ST)              // 36864
#define GSMEM (3 * STAGE)                // 110592  (x2 CTAs = 221KB/SM)

static __device__ __forceinline__ uint32_t smem_u32(const void* p) {
    uint32_t a;
    asm("{ .reg .u64 t; cvta.to.shared.u64 t, %1; cvt.u32.u64 %0, t; }"
        : "=r"(a) : "l"(p));
    return a;
}
#define LDSM_X4(r0, r1, r2, r3, addr) \
    asm volatile("ldmatrix.sync.aligned.m8n8.x4.shared.b16 {%0,%1,%2,%3}, [%4];" \
                 : "=r"(r0), "=r"(r1), "=r"(r2), "=r"(r3) : "r"(addr))
#define MMAF16(d, a, b0, b1) \
    asm volatile("mma.sync.aligned.m16n8k16.row.col.f32.f16.f16.f32 " \
                 "{%0,%1,%2,%3}, {%4,%5,%6,%7}, {%8,%9}, {%0,%1,%2,%3};" \
                 : "+f"((d)[0]), "+f"((d)[1]), "+f"((d)[2]), "+f"((d)[3]) \
                 : "r"((a)[0]), "r"((a)[1]), "r"((a)[2]), "r"((a)[3]), \
                   "r"(b0), "r"(b1))
#define CP_ASYNC16Z(saddr, gptr, sz) \
    asm volatile("cp.async.cg.shared.global [%0], [%1], 16, %2;" \
                 :: "r"(saddr), "l"(gptr), "r"(sz))
#define CP_ASYNC16(saddr, gptr) \
    asm volatile("cp.async.cg.shared.global [%0], [%1], 16;" \
                 :: "r"(saddr), "l"(gptr))

static __device__ __forceinline__ void prefetch_chunk(
    const __half* __restrict__ X16, const __half* __restrict__ XB,
    const __half* __restrict__ W16,
    uint32_t uStage, int chunk, int t, int m0, int M) {
    const int mat = chunk >> 1;
    const int k0  = (chunk & 1) << 6;
    // --- A: 128 rows x 64 halves = 8 x 16B per row -> 1024 ops, 4 iters ---
    const uint32_t uA = uStage;
#pragma unroll
    for (int it = 0; it < 4; it++) {
        const int idx = it * NTHR + t;
        const int row = idx >> 3;
        const int c16 = (idx & 7) * 8;
        const int gr  = m0 + row;
        const int ok  = (gr < M);
        const int grc = ok ? gr : (M - 1);
        const __half* ap = (mat == 0)
            ? X16 + (size_t)grc * DD + k0 + c16
            : XB  + ((size_t)grc * RR + (mat - 1)) * DD + k0 + c16;
        CP_ASYNC16Z(uA + (uint32_t)(row * CH + c16) * 2, ap, ok ? 16 : 0);
    }
    // --- B: 128 rows x 64 halves -> 1024 ops, 4 iters ---
    const __half* bp = W16 + (size_t)mat * DD * DD + k0;
    const uint32_t uB = uStage + A_ST;
#pragma unroll
    for (int it = 0; it < 4; it++) {
        const int idx = it * NTHR + t;
        const int row = idx >> 3;
        const int c16 = (idx & 7) * 8;
        CP_ASYNC16(uB + (uint32_t)(row * CH + c16) * 2, bp + row * DD + c16);
    }
}

__global__ void __launch_bounds__(NTHR, 2)
gemmK_k(const __half* __restrict__ X16, const __half* __restrict__ XB,
        const __half* __restrict__ W16,
        const float* __restrict__ bias, float* __restrict__ outF,
        __half* __restrict__ outH, int M) {
    extern __shared__ char smc[];
    const uint32_t uS = smem_u32(smc);

    const int t   = threadIdx.x;
    const int wid = t >> 5, lid = t & 31;
    const int m0  = blockIdx.x * TM;

    prefetch_chunk(X16, XB, W16, uS + 0 * STAGE, 0, t, m0, M);
    asm volatile("cp.async.commit_group;");
    prefetch_chunk(X16, XB, W16, uS + 1 * STAGE, 1, t, m0, M);
    asm volatile("cp.async.commit_group;");

    const int warpM = (wid & 3) * 32;
    const int warpN = (wid >> 2) * 64;
    const int aRow = warpM + (lid & 15);
    const int aK   = (lid >> 4) << 3;
    const int bN   = warpN + (lid & 7) + ((lid >> 4) << 3);
    const int bK   = ((lid >> 3) & 1) << 3;
    const int g    = lid >> 2;
    const int tg   = lid & 3;

    float acc[2][8][4];
#pragma unroll
    for (int i = 0; i < 2; i++)
#pragma unroll
        for (int j = 0; j < 8; j++)
#pragma unroll
            for (int c = 0; c < 4; c++) acc[i][j][c] = 0.0f;

    for (int chunk = 0; chunk < 18; chunk++) {
        __syncthreads();   // all warps done reading stage[(chunk-1)%3]
        if (chunk + 2 < 18) {
            prefetch_chunk(X16, XB, W16, uS + ((chunk + 2) % 3) * STAGE,
                           chunk + 2, t, m0, M);
            asm volatile("cp.async.commit_group;");
        }
        if (chunk < 16)       asm volatile("cp.async.wait_group 2;");
        else if (chunk == 16) asm volatile("cp.async.wait_group 1;");
        else                  asm volatile("cp.async.wait_group 0;");
        __syncthreads();

        const uint32_t uA = uS + (chunk % 3) * STAGE;
        const uint32_t uB = uA + A_ST;

#pragma unroll
        for (int ks = 0; ks < 4; ks++) {
            const int kk = ks * 16;
            uint32_t a[2][4];
#pragma unroll
            for (int mi = 0; mi < 2; mi++) {
                const uint32_t ao = (uint32_t)(((aRow + mi * 16) * CH + (aK + kk)) * 2);
                LDSM_X4(a[mi][0], a[mi][1], a[mi][2], a[mi][3], uA + ao);
            }
            uint32_t b[4][4];
#pragma unroll
            for (int bq = 0; bq < 4; bq++) {
                const uint32_t bo = (uint32_t)(((bN + bq * 16) * CH + (bK + kk)) * 2);
                LDSM_X4(b[bq][0], b[bq][1], b[bq][2], b[bq][3], uB + bo);
            }
#pragma unroll
            for (int mi = 0; mi < 2; mi++)
#pragma unroll
                for (int nj = 0; nj < 8; nj++) {
                    const int bq = nj >> 1, hi = (nj & 1) << 1;
                    MMAF16(acc[mi][nj], a[mi], b[bq][hi], b[bq][hi + 1]);
                }
        }
    }

    // Fused epilogue: layer1 -> relu + fp16 h16; layer2 -> fp32 out.
#pragma unroll
    for (int mi = 0; mi < 2; mi++) {
#pragma unroll
        for (int nj = 0; nj < 8; nj++) {
            const int col = warpN + nj * 8 + tg * 2;
            const float bx = bias[col], by = bias[col + 1];
            const int r0 = m0 + warpM + mi * 16 + g;
            const int r1 = r0 + 8;
            float2 v0 = make_float2(acc[mi][nj][0] + bx, acc[mi][nj][1] + by);
            float2 v1 = make_float2(acc[mi][nj][2] + bx, acc[mi][nj][3] + by);
            if (outH) {
                v0.x = fmaxf(v0.x, 0.f); v0.y = fmaxf(v0.y, 0.f);
                v1.x = fmaxf(v1.x, 0.f); v1.y = fmaxf(v1.y, 0.f);
                if (r0 < M)
                    *(__half2*)(outH + (size_t)r0 * DD + col) = __float22half2_rn(v0);
                if (r1 < M)
                    *(__half2*)(outH + (size_t)r1 * DD + col) = __float22half2_rn(v1);
            } else {
                if (r0 < M) *(float2*)(outF + (size_t)r0 * DD + col) = v0;
                if (r1 < M) *(float2*)(outF + (size_t)r1 * DD + col) = v1;
            }
        }
    }
}

// ---------------------------------------------------------------------------
// Launch
// ---------------------------------------------------------------------------
extern "C" void kernel_launch(void* const* d_in, const int* in_sizes, int n_in,
                              void* d_out, int out_size) {
    const float* x     = (const float*)d_in[0];
    const int*   ei    = (const int*)d_in[1];
    const int*   et    = (const int*)d_in[2];
    const float* W1    = (const float*)d_in[3];
    const float* root1 = (const float*)d_in[4];
    const float* b1    = (const float*)d_in[5];
    const float* W2    = (const float*)d_in[6];
    const float* root2 = (const float*)d_in[7];
    const float* b2    = (const float*)d_in[8];
    float* out = (float*)d_out;

    const int E = in_sizes[1] / 2;
    const int N = in_sizes[0] / DD;

    __half *x16, *h16, *xbar, *w16;
    int *cnt, *off, *cur, *bsum, *pack;
    cudaGetSymbolAddress((void**)&x16,  g_x16);
    cudaGetSymbolAddress((void**)&h16,  g_h16);
    cudaGetSymbolAddress((void**)&xbar, g_xbar);
    cudaGetSymbolAddress((void**)&w16,  g_w16);
    cudaGetSymbolAddress((void**)&cnt,  g_cnt);
    cudaGetSymbolAddress((void**)&off,  g_off);
    cudaGetSymbolAddress((void**)&cur,  g_cur);
    cudaGetSymbolAddress((void**)&bsum, g_bsum);
    cudaGetSymbolAddress((void**)&pack, g_pack);

    cudaFuncSetAttribute(gemmK_k, cudaFuncAttributeMaxDynamicSharedMemorySize, GSMEM);

    const int gemm_grid = (N + TM - 1) / TM;
    const int agg_grid  = (NN * 32 + 255) / 256;
    const int nb = (M8 + 1023) / 1024;
    const size_t n4 = (size_t)N * DD / 4;

    detect_k<<<1, 256>>>(et, E);
    zero_cnt_k<<<(M8 + 255) / 256, 256>>>(cnt);
    count_k<<<(E + 255) / 256, 256>>>(ei, et, cnt, E);
    scan1_k<<<nb, 256>>>(cnt, off, bsum, M8);
    scan2_k<<<1, 1024>>>(bsum, nb);
    scan3_k<<<(M8 + 255) / 256, 256>>>(off, cur, bsum, M8);
    scatter_k<<<(E + 255) / 256, 256>>>(ei, et, cur, pack, E);

    cvt16_k<<<(int)((n4 + 255) / 256), 256>>>(x, x16, n4);

    // Layer 1: h16 = relu( x@root1 + b1 + sum_r xbar_r@W1r )
    cvtw9_k<<<(9 * DD * DD + 255) / 256, 256>>>(root1, W1, w16);
    aggx_k<<<agg_grid, 256>>>(off, pack, x16, xbar, E);
    gemmK_k<<<gemm_grid, NTHR, GSMEM>>>(x16, xbar, w16, b1, nullptr, h16, N);

    // Layer 2: out = h@root2 + b2 + sum_r hbar_r@W2r
    cvtw9_k<<<(9 * DD * DD + 255) / 256, 256>>>(root2, W2, w16);
    aggx_k<<<agg_grid, 256>>>(off, pack, h16, xbar, E);
    gemmK_k<<<gemm_grid, NTHR, GSMEM>>>(h16, xbar, w16, b2, out, nullptr, N);
}

// round 16
// speedup vs baseline: 2.1364x; 2.1364x over previous
#include <cuda_runtime.h>
#include <cuda_fp16.h>
#include <cstdint>

#define NN 100000
#define EE 1600000
#define RR 8
#define DD 128
#define M8 (NN * RR)       // sort bins, key = dst*8 + rel

// ---------------------------------------------------------------------------
// Scratch (device globals; no allocation allowed anywhere).
// ---------------------------------------------------------------------------
__device__ __align__(16) __half g_x16[(size_t)NN * DD];        // fp16 features (layer in)
__device__ __align__(16) __half g_h16[(size_t)NN * DD];        // fp16 hidden
__device__ __align__(16) __half g_xbar[(size_t)NN * RR * DD];  // per-(dst,rel) means
__device__ __align__(16) __half g_w16[9 * DD * DD];  // [mat][n][k] weights fp16
__device__ int g_cnt[M8];
__device__ int g_off[M8];
__device__ int g_cur[M8];
__device__ int g_bsum[1024];
__device__ int g_pack[EE];     // src ids, sorted by (dst,rel)
__device__ int g_shift;        // 1 if edge arrays are int64, 0 if int32

// ---------------------------------------------------------------------------
// dtype autodetect (int64 edges => all odd 32-bit words zero)
// ---------------------------------------------------------------------------
__global__ void detect_k(const int* __restrict__ et, int E) {
    __shared__ int any;
    if (threadIdx.x == 0) any = 0;
    __syncthreads();
    int n = min(E, 4096);
    int local = 0;
    for (int i = threadIdx.x; i < n; i += blockDim.x) local |= et[2 * i + 1];
    if (local) atomicOr(&any, 1);
    __syncthreads();
    if (threadIdx.x == 0) g_shift = any ? 0 : 1;
}

// ---------------------------------------------------------------------------
// Counting sort by key (dst*8 + rel)
// ---------------------------------------------------------------------------
__global__ void zero_cnt_k(int* __restrict__ c) {
    int i = blockIdx.x * blockDim.x + threadIdx.x;
    if (i < M8) c[i] = 0;
}
__global__ void count_k(const int* __restrict__ ei, const int* __restrict__ et,
                        int* __restrict__ cnt, int E) {
    int e = blockIdx.x * blockDim.x + threadIdx.x;
    if (e < E) {
        const int sh = g_shift;
        int d = ei[(E << sh) + (e << sh)];
        int r = et[e << sh];
        if ((unsigned)d < NN && (unsigned)r < RR)
            atomicAdd(&cnt[d * RR + r], 1);
    }
}
__global__ void scan1_k(const int* __restrict__ cnt, int* __restrict__ off,
                        int* __restrict__ bsum, int M) {
    __shared__ int wsum[8];
    const int t = threadIdx.x;
    const int base = blockIdx.x * 1024 + t * 4;
    int v0 = 0, v1 = 0, v2 = 0, v3 = 0;
    if (base + 0 < M) v0 = cnt[base + 0];
    if (base + 1 < M) v1 = cnt[base + 1];
    if (base + 2 < M) v2 = cnt[base + 2];
    if (base + 3 < M) v3 = cnt[base + 3];
    const int tsum = v0 + v1 + v2 + v3;
    const int lane = t & 31, wid = t >> 5;
    int x = tsum;
#pragma unroll
    for (int o = 1; o < 32; o <<= 1) {
        int y = __shfl_up_sync(~0u, x, o);
        if (lane >= o) x += y;
    }
    if (lane == 31) wsum[wid] = x;
    __syncthreads();
    if (wid == 0) {
        int w = (lane < 8) ? wsum[lane] : 0;
#pragma unroll
        for (int o = 1; o < 8; o <<= 1) {
            int y = __shfl_up_sync(~0u, w, o);
            if (lane >= o) w += y;
        }
        if (lane < 8) wsum[lane] = w;
    }
    __syncthreads();
    const int excl = x - tsum + (wid > 0 ? wsum[wid - 1] : 0);
    if (base + 0 < M) off[base + 0] = excl;
    if (base + 1 < M) off[base + 1] = excl + v0;
    if (base + 2 < M) off[base + 2] = excl + v0 + v1;
    if (base + 3 < M) off[base + 3] = excl + v0 + v1 + v2;
    if (t == 0) bsum[blockIdx.x] = wsum[7];
}
__global__ void scan2_k(int* __restrict__ bsum, int nb) {
    __shared__ int sh[1024];
    const int t = threadIdx.x;
    sh[t] = (t < nb) ? bsum[t] : 0;
    __syncthreads();
    for (int o = 1; o < 1024; o <<= 1) {
        int v = (t >= o) ? sh[t - o] : 0;
        __syncthreads();
        sh[t] += v;
        __syncthreads();
    }
    if (t < nb) bsum[t] = (t == 0) ? 0 : sh[t - 1];
}
__global__ void scan3_k(int* __restrict__ off, int* __restrict__ cur,
                        const int* __restrict__ bsum, int M) {
    int i = blockIdx.x * blockDim.x + threadIdx.x;
    if (i < M) {
        int v = off[i] + bsum[i >> 10];
        off[i] = v;
        cur[i] = v;
    }
}
__global__ void scatter_k(const int* __restrict__ ei, const int* __restrict__ et,
                          int* __restrict__ cur, int* __restrict__ pack, int E) {
    int e = blockIdx.x * blockDim.x + threadIdx.x;
    if (e < E) {
        const int sh = g_shift;
        int s = ei[e << sh];
        int d = ei[(E << sh) + (e << sh)];
        int r = et[e << sh];
        if ((unsigned)d < NN && (unsigned)r < RR && (unsigned)s < NN) {
            int pos = atomicAdd(&cur[d * RR + r], 1);
            pack[pos] = s;
        }
    }
}

// ---------------------------------------------------------------------------
// fp32 -> fp16 feature conversion
// ---------------------------------------------------------------------------
__global__ void cvt16_k(const float* __restrict__ A, __half* __restrict__ B, size_t n4) {
    size_t i = (size_t)blockIdx.x * blockDim.x + threadIdx.x;
    if (i < n4) {
        float4 v = ((const float4*)A)[i];
        __half2 a = __float22half2_rn(make_float2(v.x, v.y));
        __half2 b = __float22half2_rn(make_float2(v.z, v.w));
        ((__half2*)B)[2 * i]     = a;
        ((__half2*)B)[2 * i + 1] = b;
    }
}

// ---------------------------------------------------------------------------
// Weight transpose to fp16: out[mat][n][k]; mat0=root, 1..8=W[r]
// ---------------------------------------------------------------------------
__global__ void cvtw9_k(const float* __restrict__ root, const float* __restrict__ W,
                        __half* __restrict__ H) {
    int idx = blockIdx.x * blockDim.x + threadIdx.x;
    if (idx < 9 * DD * DD) {
        int mat = idx >> 14;
        int rem = idx & 16383;
        int n = rem >> 7;
        int k = rem & 127;
        float v = (mat == 0) ? root[(k << 7) + n] : W[((mat - 1) << 14) + (k << 7) + n];
        H[idx] = __float2half_rn(v);
    }
}

// ---------------------------------------------------------------------------
// Gather-mean: xbar[d][r] = mean over edges (sorted (dst,rel)) of src16[src].
// One warp per dst; gathers hit the 25.6MB L2-resident fp16 feature buffer.
// 4-way unrolled gather for MLP.
// ---------------------------------------------------------------------------
__global__ void aggx_k(const int* __restrict__ off, const int* __restrict__ pack,
                       const __half* __restrict__ src16, __half* __restrict__ xbar,
                       int E) {
    const int d = (blockIdx.x * blockDim.x + threadIdx.x) >> 5;
    if (d >= NN) return;
    const int lane = threadIdx.x & 31;
    const int base = d * RR;

    int v = E;
    if (lane < 9 && base + lane < M8) v = off[base + lane];

    const int c4 = lane * 4;
#pragma unroll
    for (int r = 0; r < RR; r++) {
        const int lo = __shfl_sync(~0u, v, r);
        const int hi = __shfl_sync(~0u, v, r + 1);
        float4 acc = make_float4(0.f, 0.f, 0.f, 0.f);
        int i = lo;
        for (; i + 4 <= hi; i += 4) {
            const int s0 = pack[i],     s1 = pack[i + 1];
            const int s2 = pack[i + 2], s3 = pack[i + 3];
            const float2 q0 = *(const float2*)(src16 + (size_t)s0 * DD + c4);
            const float2 q1 = *(const float2*)(src16 + (size_t)s1 * DD + c4);
            const float2 q2 = *(const float2*)(src16 + (size_t)s2 * DD + c4);
            const float2 q3 = *(const float2*)(src16 + (size_t)s3 * DD + c4);
            float2 f;
            f = __half22float2(*(const __half2*)&q0.x); acc.x += f.x; acc.y += f.y;
            f = __half22float2(*(const __half2*)&q0.y); acc.z += f.x; acc.w += f.y;
            f = __half22float2(*(const __half2*)&q1.x); acc.x += f.x; acc.y += f.y;
            f = __half22float2(*(const __half2*)&q1.y); acc.z += f.x; acc.w += f.y;
            f = __half22float2(*(const __half2*)&q2.x); acc.x += f.x; acc.y += f.y;
            f = __half22float2(*(const __half2*)&q2.y); acc.z += f.x; acc.w += f.y;
            f = __half22float2(*(const __half2*)&q3.x); acc.x += f.x; acc.y += f.y;
            f = __half22float2(*(const __half2*)&q3.y); acc.z += f.x; acc.w += f.y;
        }
        for (; i < hi; i++) {
            const int s = pack[i];
            const float2 q = *(const float2*)(src16 + (size_t)s * DD + c4);
            float2 f;
            f = __half22float2(*(const __half2*)&q.x); acc.x += f.x; acc.y += f.y;
            f = __half22float2(*(const __half2*)&q.y); acc.z += f.x; acc.w += f.y;
        }
        const float inv = (hi > lo) ? (1.0f / (float)(hi - lo)) : 0.f;
        __half2 o0 = __float22half2_rn(make_float2(acc.x * inv, acc.y * inv));
        __half2 o1 = __float22half2_rn(make_float2(acc.z * inv, acc.w * inv));
        float2 ov;
        *(__half2*)&ov.x = o0;
        *(__half2*)&ov.y = o1;
        *(float2*)(xbar + ((size_t)base + r) * DD + c4) = ov;
    }
}

// ---------------------------------------------------------------------------
// K=1152 GEMM: out = act( concat(x16, xbar_0..7)[M,1152] @ Wcat[1152,128] + b )
// 256 threads (8 warps, 4m x 2n), tile M=128 x N=128, 2 CTAs/SM.
// 18 k-half chunks (9 mats x 2 halves of 64) through a 3-stage cp.async ring.
// Single fp16 MMA pass; fp32 accumulate; fused bias/relu epilogue.
// ---------------------------------------------------------------------------
#define TM 128
#define NTHR 256
#define CH 72                            // chunk row stride (64 data + 8 pad)
#define A_ST (TM * CH * 2)               // 18432
#define B_ST (128 * CH * 2)              // 18432
#define STAGE (A_ST + B_ST)              // 36864
#define GSMEM (3 * STAGE)                // 110592  (x2 CTAs = 221KB/SM)

static __device__ __forceinline__ uint32_t smem_u32(const void* p) {
    uint32_t a;
    asm("{ .reg .u64 t; cvta.to.shared.u64 t, %1; cvt.u32.u64 %0, t; }"
        : "=r"(a) : "l"(p));
    return a;
}
#define LDSM_X4(r0, r1, r2, r3, addr) \
    asm volatile("ldmatrix.sync.aligned.m8n8.x4.shared.b16 {%0,%1,%2,%3}, [%4];" \
                 : "=r"(r0), "=r"(r1), "=r"(r2), "=r"(r3) : "r"(addr))
#define MMAF16(d, a, b0, b1) \
    asm volatile("mma.sync.aligned.m16n8k16.row.col.f32.f16.f16.f32 " \
                 "{%0,%1,%2,%3}, {%4,%5,%6,%7}, {%8,%9}, {%0,%1,%2,%3};" \
                 : "+f"((d)[0]), "+f"((d)[1]), "+f"((d)[2]), "+f"((d)[3]) \
                 : "r"((a)[0]), "r"((a)[1]), "r"((a)[2]), "r"((a)[3]), \
                   "r"(b0), "r"(b1))
#define CP_ASYNC16Z(saddr, gptr, sz) \
    asm volatile("cp.async.cg.shared.global [%0], [%1], 16, %2;" \
                 :: "r"(saddr), "l"(gptr), "r"(sz))
#define CP_ASYNC16(saddr, gptr) \
    asm volatile("cp.async.cg.shared.global [%0], [%1], 16;" \
                 :: "r"(saddr), "l"(gptr))

static __device__ __forceinline__ void prefetch_chunk(
    const __half* __restrict__ X16, const __half* __restrict__ XB,
    const __half* __restrict__ W16,
    uint32_t uStage, int chunk, int t, int m0, int M) {
    const int mat = chunk >> 1;
    const int k0  = (chunk & 1) << 6;
    // --- A: 128 rows x 64 halves = 8 x 16B per row -> 1024 ops, 4 iters ---
    const uint32_t uA = uStage;
#pragma unroll
    for (int it = 0; it < 4; it++) {
        const int idx = it * NTHR + t;
        const int row = idx >> 3;
        const int c16 = (idx & 7) * 8;
        const int gr  = m0 + row;
        const int ok  = (gr < M);
        const int grc = ok ? gr : (M - 1);
        const __half* ap = (mat == 0)
            ? X16 + (size_t)grc * DD + k0 + c16
            : XB  + ((size_t)grc * RR + (mat - 1)) * DD + k0 + c16;
        CP_ASYNC16Z(uA + (uint32_t)(row * CH + c16) * 2, ap, ok ? 16 : 0);
    }
    // --- B: 128 rows x 64 halves -> 1024 ops, 4 iters ---
    const __half* bp = W16 + (size_t)mat * DD * DD + k0;
    const uint32_t uB = uStage + A_ST;
#pragma unroll
    for (int it = 0; it < 4; it++) {
        const int idx = it * NTHR + t;
        const int row = idx >> 3;
        const int c16 = (idx & 7) * 8;
        CP_ASYNC16(uB + (uint32_t)(row * CH + c16) * 2, bp + row * DD + c16);
    }
}

__global__ void __launch_bounds__(NTHR, 2)
gemmK_k(const __half* __restrict__ X16, const __half* __restrict__ XB,
        const __half* __restrict__ W16,
        const float* __restrict__ bias, float* __restrict__ outF,
        __half* __restrict__ outH, int M) {
    extern __shared__ char smc[];
    const uint32_t uS = smem_u32(smc);

    const int t   = threadIdx.x;
    const int wid = t >> 5, lid = t & 31;
    const int m0  = blockIdx.x * TM;

    prefetch_chunk(X16, XB, W16, uS + 0 * STAGE, 0, t, m0, M);
    asm volatile("cp.async.commit_group;");
    prefetch_chunk(X16, XB, W16, uS + 1 * STAGE, 1, t, m0, M);
    asm volatile("cp.async.commit_group;");

    const int warpM = (wid & 3) * 32;
    const int warpN = (wid >> 2) * 64;
    const int aRow = warpM + (lid & 15);
    const int aK   = (lid >> 4) << 3;
    const int bN   = warpN + (lid & 7) + ((lid >> 4) << 3);
    const int bK   = ((lid >> 3) & 1) << 3;
    const int g    = lid >> 2;
    const int tg   = lid & 3;

    float acc[2][8][4];
#pragma unroll
    for (int i = 0; i < 2; i++)
#pragma unroll
        for (int j = 0; j < 8; j++)
#pragma unroll
            for (int c = 0; c < 4; c++) acc[i][j][c] = 0.0f;

    for (int chunk = 0; chunk < 18; chunk++) {
        __syncthreads();   // all warps done reading stage[(chunk-1)%3]
        if (chunk + 2 < 18) {
            prefetch_chunk(X16, XB, W16, uS + ((chunk + 2) % 3) * STAGE,
                           chunk + 2, t, m0, M);
            asm volatile("cp.async.commit_group;");
        }
        if (chunk < 16)       asm volatile("cp.async.wait_group 2;");
        else if (chunk == 16) asm volatile("cp.async.wait_group 1;");
        else                  asm volatile("cp.async.wait_group 0;");
        __syncthreads();

        const uint32_t uA = uS + (chunk % 3) * STAGE;
        const uint32_t uB = uA + A_ST;

#pragma unroll
        for (int ks = 0; ks < 4; ks++) {
            const int kk = ks * 16;
            uint32_t a[2][4];
#pragma unroll
            for (int mi = 0; mi < 2; mi++) {
                const uint32_t ao = (uint32_t)(((aRow + mi * 16) * CH + (aK + kk)) * 2);
                LDSM_X4(a[mi][0], a[mi][1], a[mi][2], a[mi][3], uA + ao);
            }
            uint32_t b[4][4];
#pragma unroll
            for (int bq = 0; bq < 4; bq++) {
                const uint32_t bo = (uint32_t)(((bN + bq * 16) * CH + (bK + kk)) * 2);
                LDSM_X4(b[bq][0], b[bq][1], b[bq][2], b[bq][3], uB + bo);
            }
#pragma unroll
            for (int mi = 0; mi < 2; mi++)
#pragma unroll
                for (int nj = 0; nj < 8; nj++) {
                    const int bq = nj >> 1, hi = (nj & 1) << 1;
                    MMAF16(acc[mi][nj], a[mi], b[bq][hi], b[bq][hi + 1]);
                }
        }
    }

    // Fused epilogue: layer1 -> relu + fp16 h16; layer2 -> fp32 out.
#pragma unroll
    for (int mi = 0; mi < 2; mi++) {
#pragma unroll
        for (int nj = 0; nj < 8; nj++) {
            const int col = warpN + nj * 8 + tg * 2;
            const float bx = bias[col], by = bias[col + 1];
            const int r0 = m0 + warpM + mi * 16 + g;
            const int r1 = r0 + 8;
            float2 v0 = make_float2(acc[mi][nj][0] + bx, acc[mi][nj][1] + by);
            float2 v1 = make_float2(acc[mi][nj][2] + bx, acc[mi][nj][3] + by);
            if (outH) {
                v0.x = fmaxf(v0.x, 0.f); v0.y = fmaxf(v0.y, 0.f);
                v1.x = fmaxf(v1.x, 0.f); v1.y = fmaxf(v1.y, 0.f);
                if (r0 < M)
                    *(__half2*)(outH + (size_t)r0 * DD + col) = __float22half2_rn(v0);
                if (r1 < M)
                    *(__half2*)(outH + (size_t)r1 * DD + col) = __float22half2_rn(v1);
            } else {
                if (r0 < M) *(float2*)(outF + (size_t)r0 * DD + col) = v0;
                if (r1 < M) *(float2*)(outF + (size_t)r1 * DD + col) = v1;
            }
        }
    }
}

// ---------------------------------------------------------------------------
// Launch
// ---------------------------------------------------------------------------
extern "C" void kernel_launch(void* const* d_in, const int* in_sizes, int n_in,
                              void* d_out, int out_size) {
    const float* x     = (const float*)d_in[0];
    const int*   ei    = (const int*)d_in[1];
    const int*   et    = (const int*)d_in[2];
    const float* W1    = (const float*)d_in[3];
    const float* root1 = (const float*)d_in[4];
    const float* b1    = (const float*)d_in[5];
    const float* W2    = (const float*)d_in[6];
    const float* root2 = (const float*)d_in[7];
    const float* b2    = (const float*)d_in[8];
    float* out = (float*)d_out;

    const int E = in_sizes[1] / 2;
    const int N = in_sizes[0] / DD;

    __half *x16, *h16, *xbar, *w16;
    int *cnt, *off, *cur, *bsum, *pack;
    cudaGetSymbolAddress((void**)&x16,  g_x16);
    cudaGetSymbolAddress((void**)&h16,  g_h16);
    cudaGetSymbolAddress((void**)&xbar, g_xbar);
    cudaGetSymbolAddress((void**)&w16,  g_w16);
    cudaGetSymbolAddress((void**)&cnt,  g_cnt);
    cudaGetSymbolAddress((void**)&off,  g_off);
    cudaGetSymbolAddress((void**)&cur,  g_cur);
    cudaGetSymbolAddress((void**)&bsum, g_bsum);
    cudaGetSymbolAddress((void**)&pack, g_pack);

    cudaFuncSetAttribute(gemmK_k, cudaFuncAttributeMaxDynamicSharedMemorySize, GSMEM);

    const int gemm_grid = (N + TM - 1) / TM;
    const int agg_grid  = (NN * 32 + 255) / 256;
    const int nb = (M8 + 1023) / 1024;
    const size_t n4 = (size_t)N * DD / 4;

    detect_k<<<1, 256>>>(et, E);
    zero_cnt_k<<<(M8 + 255) / 256, 256>>>(cnt);
    count_k<<<(E + 255) / 256, 256>>>(ei, et, cnt, E);
    scan1_k<<<nb, 256>>>(cnt, off, bsum, M8);
    scan2_k<<<1, 1024>>>(bsum, nb);
    scan3_k<<<(M8 + 255) / 256, 256>>>(off, cur, bsum, M8);
    scatter_k<<<(E + 255) / 256, 256>>>(ei, et, cur, pack, E);

    cvt16_k<<<(int)((n4 + 255) / 256), 256>>>(x, x16, n4);

    // Layer 1: h16 = relu( x@root1 + b1 + sum_r xbar_r@W1r )
    cvtw9_k<<<(9 * DD * DD + 255) / 256, 256>>>(root1, W1, w16);
    aggx_k<<<agg_grid, 256>>>(off, pack, x16, xbar, E);
    gemmK_k<<<gemm_grid, NTHR, GSMEM>>>(x16, xbar, w16, b1, nullptr, h16, N);

    // Layer 2: out = h@root2 + b2 + sum_r hbar_r@W2r
    cvtw9_k<<<(9 * DD * DD + 255) / 256, 256>>>(root2, W2, w16);
    aggx_k<<<agg_grid, 256>>>(off, pack, h16, xbar, E);
    gemmK_k<<<gemm_grid, NTHR, GSMEM>>>(h16, xbar, w16, b2, out, nullptr, N);
}

// round 17
// speedup vs baseline: 2.1472x; 1.0050x over previous
#include <cuda_runtime.h>
#include <cuda_fp16.h>
#include <cstdint>

#define NN 100000
#define EE 1600000
#define RR 8
#define DD 128
#define M8 (NN * RR)       // sort bins, key = dst*8 + rel

// ---------------------------------------------------------------------------
// Scratch (device globals; no allocation allowed anywhere).
// ---------------------------------------------------------------------------
__device__ __align__(16) __half g_x16[(size_t)NN * DD];        // fp16 features (layer in)
__device__ __align__(16) __half g_h16[(size_t)NN * DD];        // fp16 hidden
__device__ __align__(16) __half g_xbar[(size_t)NN * RR * DD];  // per-(dst,rel) means
__device__ __align__(16) __half g_w16[18 * DD * DD];  // [mat][n][k] weights fp16 (both layers)
__device__ int g_cnt[M8];
__device__ int g_off[M8];
__device__ int g_cur[M8];
__device__ int g_bsum[1024];
__device__ int g_pack[EE];     // src ids, sorted by (dst,rel)
__device__ int g_shift;        // 1 if edge arrays are int64, 0 if int32

// ---------------------------------------------------------------------------
// dtype autodetect (int64 edges => all odd 32-bit words zero)
// ---------------------------------------------------------------------------
__global__ void detect_k(const int* __restrict__ et, int E) {
    __shared__ int any;
    if (threadIdx.x == 0) any = 0;
    __syncthreads();
    int n = min(E, 4096);
    int local = 0;
    for (int i = threadIdx.x; i < n; i += blockDim.x) local |= et[2 * i + 1];
    if (local) atomicOr(&any, 1);
    __syncthreads();
    if (threadIdx.x == 0) g_shift = any ? 0 : 1;
}

// ---------------------------------------------------------------------------
// Counting sort by key (dst*8 + rel)
// ---------------------------------------------------------------------------
__global__ void zero_cnt_k(int* __restrict__ c) {
    int i = blockIdx.x * blockDim.x + threadIdx.x;
    if (i < M8) c[i] = 0;
}
__global__ void count_k(const int* __restrict__ ei, const int* __restrict__ et,
                        int* __restrict__ cnt, int E) {
    int e = blockIdx.x * blockDim.x + threadIdx.x;
    if (e < E) {
        const int sh = g_shift;
        int d = ei[(E << sh) + (e << sh)];
        int r = et[e << sh];
        if ((unsigned)d < NN && (unsigned)r < RR)
            atomicAdd(&cnt[d * RR + r], 1);
    }
}
__global__ void scan1_k(const int* __restrict__ cnt, int* __restrict__ off,
                        int* __restrict__ bsum, int M) {
    __shared__ int wsum[8];
    const int t = threadIdx.x;
    const int base = blockIdx.x * 1024 + t * 4;
    int v0 = 0, v1 = 0, v2 = 0, v3 = 0;
    if (base + 0 < M) v0 = cnt[base + 0];
    if (base + 1 < M) v1 = cnt[base + 1];
    if (base + 2 < M) v2 = cnt[base + 2];
    if (base + 3 < M) v3 = cnt[base + 3];
    const int tsum = v0 + v1 + v2 + v3;
    const int lane = t & 31, wid = t >> 5;
    int x = tsum;
#pragma unroll
    for (int o = 1; o < 32; o <<= 1) {
        int y = __shfl_up_sync(~0u, x, o);
        if (lane >= o) x += y;
    }
    if (lane == 31) wsum[wid] = x;
    __syncthreads();
    if (wid == 0) {
        int w = (lane < 8) ? wsum[lane] : 0;
#pragma unroll
        for (int o = 1; o < 8; o <<= 1) {
            int y = __shfl_up_sync(~0u, w, o);
            if (lane >= o) w += y;
        }
        if (lane < 8) wsum[lane] = w;
    }
    __syncthreads();
    const int excl = x - tsum + (wid > 0 ? wsum[wid - 1] : 0);
    if (base + 0 < M) off[base + 0] = excl;
    if (base + 1 < M) off[base + 1] = excl + v0;
    if (base + 2 < M) off[base + 2] = excl + v0 + v1;
    if (base + 3 < M) off[base + 3] = excl + v0 + v1 + v2;
    if (t == 0) bsum[blockIdx.x] = wsum[7];
}
__global__ void scan2_k(int* __restrict__ bsum, int nb) {
    __shared__ int sh[1024];
    const int t = threadIdx.x;
    sh[t] = (t < nb) ? bsum[t] : 0;
    __syncthreads();
    for (int o = 1; o < 1024; o <<= 1) {
        int v = (t >= o) ? sh[t - o] : 0;
        __syncthreads();
        sh[t] += v;
        __syncthreads();
    }
    if (t < nb) bsum[t] = (t == 0) ? 0 : sh[t - 1];
}
__global__ void scan3_k(int* __restrict__ off, int* __restrict__ cur,
                        const int* __restrict__ bsum, int M) {
    int i = blockIdx.x * blockDim.x + threadIdx.x;
    if (i < M) {
        int v = off[i] + bsum[i >> 10];
        off[i] = v;
        cur[i] = v;
    }
}
__global__ void scatter_k(const int* __restrict__ ei, const int* __restrict__ et,
                          int* __restrict__ cur, int* __restrict__ pack, int E) {
    int e = blockIdx.x * blockDim.x + threadIdx.x;
    if (e < E) {
        const int sh = g_shift;
        int s = ei[e << sh];
        int d = ei[(E << sh) + (e << sh)];
        int r = et[e << sh];
        if ((unsigned)d < NN && (unsigned)r < RR && (unsigned)s < NN) {
            int pos = atomicAdd(&cur[d * RR + r], 1);
            pack[pos] = s;
        }
    }
}

// ---------------------------------------------------------------------------
// fp32 -> fp16 feature conversion
// ---------------------------------------------------------------------------
__global__ void cvt16_k(const float* __restrict__ A, __half* __restrict__ B, size_t n4) {
    size_t i = (size_t)blockIdx.x * blockDim.x + threadIdx.x;
    if (i < n4) {
        float4 v = ((const float4*)A)[i];
        __half2 a = __float22half2_rn(make_float2(v.x, v.y));
        __half2 b = __float22half2_rn(make_float2(v.z, v.w));
        ((__half2*)B)[2 * i]     = a;
        ((__half2*)B)[2 * i + 1] = b;
    }
}

// ---------------------------------------------------------------------------
// Weight transpose to fp16 for BOTH layers: out[mat][n][k]
// mat 0 = root1, 1..8 = W1[r], 9 = root2, 10..17 = W2[r]
// ---------------------------------------------------------------------------
__global__ void cvtw18_k(const float* __restrict__ root1, const float* __restrict__ W1,
                         const float* __restrict__ root2, const float* __restrict__ W2,
                         __half* __restrict__ H) {
    int idx = blockIdx.x * blockDim.x + threadIdx.x;
    if (idx < 18 * DD * DD) {
        int mat = idx >> 14;
        int rem = idx & 16383;
        int n = rem >> 7;
        int k = rem & 127;
        float v;
        if (mat == 0)      v = root1[(k << 7) + n];
        else if (mat < 9)  v = W1[((mat - 1) << 14) + (k << 7) + n];
        else if (mat == 9) v = root2[(k << 7) + n];
        else               v = W2[((mat - 10) << 14) + (k << 7) + n];
        H[idx] = __float2half_rn(v);
    }
}

// ---------------------------------------------------------------------------
// Gather-mean: xbar[d][r] = mean over edges (sorted (dst,rel)) of src16[src].
// One warp per dst; gathers hit the 25.6MB L2-resident fp16 feature buffer.
// 4-way unrolled gather for MLP. (Frozen: R12 form.)
// ---------------------------------------------------------------------------
__global__ void aggx_k(const int* __restrict__ off, const int* __restrict__ pack,
                       const __half* __restrict__ src16, __half* __restrict__ xbar,
                       int E) {
    const int d = (blockIdx.x * blockDim.x + threadIdx.x) >> 5;
    if (d >= NN) return;
    const int lane = threadIdx.x & 31;
    const int base = d * RR;

    int v = E;
    if (lane < 9 && base + lane < M8) v = off[base + lane];

    const int c4 = lane * 4;
#pragma unroll
    for (int r = 0; r < RR; r++) {
        const int lo = __shfl_sync(~0u, v, r);
        const int hi = __shfl_sync(~0u, v, r + 1);
        float4 acc = make_float4(0.f, 0.f, 0.f, 0.f);
        int i = lo;
        for (; i + 4 <= hi; i += 4) {
            const int s0 = pack[i],     s1 = pack[i + 1];
            const int s2 = pack[i + 2], s3 = pack[i + 3];
            const float2 q0 = *(const float2*)(src16 + (size_t)s0 * DD + c4);
            const float2 q1 = *(const float2*)(src16 + (size_t)s1 * DD + c4);
            const float2 q2 = *(const float2*)(src16 + (size_t)s2 * DD + c4);
            const float2 q3 = *(const float2*)(src16 + (size_t)s3 * DD + c4);
            float2 f;
            f = __half22float2(*(const __half2*)&q0.x); acc.x += f.x; acc.y += f.y;
            f = __half22float2(*(const __half2*)&q0.y); acc.z += f.x; acc.w += f.y;
            f = __half22float2(*(const __half2*)&q1.x); acc.x += f.x; acc.y += f.y;
            f = __half22float2(*(const __half2*)&q1.y); acc.z += f.x; acc.w += f.y;
            f = __half22float2(*(const __half2*)&q2.x); acc.x += f.x; acc.y += f.y;
            f = __half22float2(*(const __half2*)&q2.y); acc.z += f.x; acc.w += f.y;
            f = __half22float2(*(const __half2*)&q3.x); acc.x += f.x; acc.y += f.y;
            f = __half22float2(*(const __half2*)&q3.y); acc.z += f.x; acc.w += f.y;
        }
        for (; i < hi; i++) {
            const int s = pack[i];
            const float2 q = *(const float2*)(src16 + (size_t)s * DD + c4);
            float2 f;
            f = __half22float2(*(const __half2*)&q.x); acc.x += f.x; acc.y += f.y;
            f = __half22float2(*(const __half2*)&q.y); acc.z += f.x; acc.w += f.y;
        }
        const float inv = (hi > lo) ? (1.0f / (float)(hi - lo)) : 0.f;
        __half2 o0 = __float22half2_rn(make_float2(acc.x * inv, acc.y * inv));
        __half2 o1 = __float22half2_rn(make_float2(acc.z * inv, acc.w * inv));
        float2 ov;
        *(__half2*)&ov.x = o0;
        *(__half2*)&ov.y = o1;
        *(float2*)(xbar + ((size_t)base + r) * DD + c4) = ov;
    }
}

// ---------------------------------------------------------------------------
// K=1152 GEMM, persistent tiles: out = act(concat(x16,xbar)@Wcat + b).
// 256 threads (8 warps, 4m x 2n), tile M=128 x N=128, 2 CTAs/SM; each CTA
// loops over m-tiles (tile += gridDim.x) -> no partial last wave.
// Per tile: 18 k-half chunks through a 3-stage cp.async ring, single fp16
// MMA pass, fp32 accumulate, fused bias/relu epilogue.
// ---------------------------------------------------------------------------
#define TM 128
#define NTHR 256
#define CH 72                            // chunk row stride (64 data + 8 pad)
#define A_ST (TM * CH * 2)               // 18432
#define B_ST (128 * CH * 2)              // 18432
#define STAGE (A_ST + B_ST)              // 36864
#define GSMEM (3 * STAGE)                // 110592  (x2 CTAs = 221KB/SM)

static __device__ __forceinline__ uint32_t smem_u32(const void* p) {
    uint32_t a;
    asm("{ .reg .u64 t; cvta.to.shared.u64 t, %1; cvt.u32.u64 %0, t; }"
        : "=r"(a) : "l"(p));
    return a;
}
#define LDSM_X4(r0, r1, r2, r3, addr) \
    asm volatile("ldmatrix.sync.aligned.m8n8.x4.shared.b16 {%0,%1,%2,%3}, [%4];" \
                 : "=r"(r0), "=r"(r1), "=r"(r2), "=r"(r3) : "r"(addr))
#define MMAF16(d, a, b0, b1) \
    asm volatile("mma.sync.aligned.m16n8k16.row.col.f32.f16.f16.f32 " \
                 "{%0,%1,%2,%3}, {%4,%5,%6,%7}, {%8,%9}, {%0,%1,%2,%3};" \
                 : "+f"((d)[0]), "+f"((d)[1]), "+f"((d)[2]), "+f"((d)[3]) \
                 : "r"((a)[0]), "r"((a)[1]), "r"((a)[2]), "r"((a)[3]), \
                   "r"(b0), "r"(b1))
#define CP_ASYNC16Z(saddr, gptr, sz) \
    asm volatile("cp.async.cg.shared.global [%0], [%1], 16, %2;" \
                 :: "r"(saddr), "l"(gptr), "r"(sz))
#define CP_ASYNC16(saddr, gptr) \
    asm volatile("cp.async.cg.shared.global [%0], [%1], 16;" \
                 :: "r"(saddr), "l"(gptr))

static __device__ __forceinline__ void prefetch_chunk(
    const __half* __restrict__ X16, const __half* __restrict__ XB,
    const __half* __restrict__ W16,
    uint32_t uStage, int chunk, int t, int m0, int M) {
    const int mat = chunk >> 1;
    const int k0  = (chunk & 1) << 6;
    // --- A: 128 rows x 64 halves = 8 x 16B per row -> 1024 ops, 4 iters ---
    const uint32_t uA = uStage;
#pragma unroll
    for (int it = 0; it < 4; it++) {
        const int idx = it * NTHR + t;
        const int row = idx >> 3;
        const int c16 = (idx & 7) * 8;
        const int gr  = m0 + row;
        const int ok  = (gr < M);
        const int grc = ok ? gr : (M - 1);
        const __half* ap = (mat == 0)
            ? X16 + (size_t)grc * DD + k0 + c16
            : XB  + ((size_t)grc * RR + (mat - 1)) * DD + k0 + c16;
        CP_ASYNC16Z(uA + (uint32_t)(row * CH + c16) * 2, ap, ok ? 16 : 0);
    }
    // --- B: 128 rows x 64 halves -> 1024 ops, 4 iters ---
    const __half* bp = W16 + (size_t)mat * DD * DD + k0;
    const uint32_t uB = uStage + A_ST;
#pragma unroll
    for (int it = 0; it < 4; it++) {
        const int idx = it * NTHR + t;
        const int row = idx >> 3;
        const int c16 = (idx & 7) * 8;
        CP_ASYNC16(uB + (uint32_t)(row * CH + c16) * 2, bp + row * DD + c16);
    }
}

__global__ void __launch_bounds__(NTHR, 2)
gemmK_k(const __half* __restrict__ X16, const __half* __restrict__ XB,
        const __half* __restrict__ W16,
        const float* __restrict__ bias, float* __restrict__ outF,
        __half* __restrict__ outH, int M, int ntiles) {
    extern __shared__ char smc[];
    const uint32_t uS = smem_u32(smc);

    const int t   = threadIdx.x;
    const int wid = t >> 5, lid = t & 31;

    const int warpM = (wid & 3) * 32;
    const int warpN = (wid >> 2) * 64;
    const int aRow = warpM + (lid & 15);
    const int aK   = (lid >> 4) << 3;
    const int bN   = warpN + (lid & 7) + ((lid >> 4) << 3);
    const int bK   = ((lid >> 3) & 1) << 3;
    const int g    = lid >> 2;
    const int tg   = lid & 3;

    for (int tile = blockIdx.x; tile < ntiles; tile += gridDim.x) {
        const int m0 = tile * TM;

        // Per-tile prologue: stages 0/1. Laggard warps of the previous tile
        // are at worst still reading stage 2 (chunk 17) -> no conflict.
        prefetch_chunk(X16, XB, W16, uS + 0 * STAGE, 0, t, m0, M);
        asm volatile("cp.async.commit_group;");
        prefetch_chunk(X16, XB, W16, uS + 1 * STAGE, 1, t, m0, M);
        asm volatile("cp.async.commit_group;");

        float acc[2][8][4];
#pragma unroll
        for (int i = 0; i < 2; i++)
#pragma unroll
            for (int j = 0; j < 8; j++)
#pragma unroll
                for (int c = 0; c < 4; c++) acc[i][j][c] = 0.0f;

        for (int chunk = 0; chunk < 18; chunk++) {
            __syncthreads();   // all warps done reading stage[(chunk-1)%3]
            if (chunk + 2 < 18) {
                prefetch_chunk(X16, XB, W16, uS + ((chunk + 2) % 3) * STAGE,
                               chunk + 2, t, m0, M);
                asm volatile("cp.async.commit_group;");
            }
            if (chunk < 16)       asm volatile("cp.async.wait_group 2;");
            else if (chunk == 16) asm volatile("cp.async.wait_group 1;");
            else                  asm volatile("cp.async.wait_group 0;");
            __syncthreads();

            const uint32_t uA = uS + (chunk % 3) * STAGE;
            const uint32_t uB = uA + A_ST;

#pragma unroll
            for (int ks = 0; ks < 4; ks++) {
                const int kk = ks * 16;
                uint32_t a[2][4];
#pragma unroll
                for (int mi = 0; mi < 2; mi++) {
                    const uint32_t ao = (uint32_t)(((aRow + mi * 16) * CH + (aK + kk)) * 2);
                    LDSM_X4(a[mi][0], a[mi][1], a[mi][2], a[mi][3], uA + ao);
                }
                uint32_t b[4][4];
#pragma unroll
                for (int bq = 0; bq < 4; bq++) {
                    const uint32_t bo = (uint32_t)(((bN + bq * 16) * CH + (bK + kk)) * 2);
                    LDSM_X4(b[bq][0], b[bq][1], b[bq][2], b[bq][3], uB + bo);
                }
#pragma unroll
                for (int mi = 0; mi < 2; mi++)
#pragma unroll
                    for (int nj = 0; nj < 8; nj++) {
                        const int bq = nj >> 1, hi = (nj & 1) << 1;
                        MMAF16(acc[mi][nj], a[mi], b[bq][hi], b[bq][hi + 1]);
                    }
            }
        }

        // Fused epilogue: layer1 -> relu + fp16 h16; layer2 -> fp32 out.
#pragma unroll
        for (int mi = 0; mi < 2; mi++) {
#pragma unroll
            for (int nj = 0; nj < 8; nj++) {
                const int col = warpN + nj * 8 + tg * 2;
                const float bx = bias[col], by = bias[col + 1];
                const int r0 = m0 + warpM + mi * 16 + g;
                const int r1 = r0 + 8;
                float2 v0 = make_float2(acc[mi][nj][0] + bx, acc[mi][nj][1] + by);
                float2 v1 = make_float2(acc[mi][nj][2] + bx, acc[mi][nj][3] + by);
                if (outH) {
                    v0.x = fmaxf(v0.x, 0.f); v0.y = fmaxf(v0.y, 0.f);
                    v1.x = fmaxf(v1.x, 0.f); v1.y = fmaxf(v1.y, 0.f);
                    if (r0 < M)
                        *(__half2*)(outH + (size_t)r0 * DD + col) = __float22half2_rn(v0);
                    if (r1 < M)
                        *(__half2*)(outH + (size_t)r1 * DD + col) = __float22half2_rn(v1);
                } else {
                    if (r0 < M) *(float2*)(outF + (size_t)r0 * DD + col) = v0;
                    if (r1 < M) *(float2*)(outF + (size_t)r1 * DD + col) = v1;
                }
            }
        }
    }
}

// ---------------------------------------------------------------------------
// Launch
// ---------------------------------------------------------------------------
extern "C" void kernel_launch(void* const* d_in, const int* in_sizes, int n_in,
                              void* d_out, int out_size) {
    const float* x     = (const float*)d_in[0];
    const int*   ei    = (const int*)d_in[1];
    const int*   et    = (const int*)d_in[2];
    const float* W1    = (const float*)d_in[3];
    const float* root1 = (const float*)d_in[4];
    const float* b1    = (const float*)d_in[5];
    const float* W2    = (const float*)d_in[6];
    const float* root2 = (const float*)d_in[7];
    const float* b2    = (const float*)d_in[8];
    float* out = (float*)d_out;

    const int E = in_sizes[1] / 2;
    const int N = in_sizes[0] / DD;

    __half *x16, *h16, *xbar, *w16;
    int *cnt, *off, *cur, *bsum, *pack;
    cudaGetSymbolAddress((void**)&x16,  g_x16);
    cudaGetSymbolAddress((void**)&h16,  g_h16);
    cudaGetSymbolAddress((void**)&xbar, g_xbar);
    cudaGetSymbolAddress((void**)&w16,  g_w16);
    cudaGetSymbolAddress((void**)&cnt,  g_cnt);
    cudaGetSymbolAddress((void**)&off,  g_off);
    cudaGetSymbolAddress((void**)&cur,  g_cur);
    cudaGetSymbolAddress((void**)&bsum, g_bsum);
    cudaGetSymbolAddress((void**)&pack, g_pack);

    cudaFuncSetAttribute(gemmK_k, cudaFuncAttributeMaxDynamicSharedMemorySize, GSMEM);

    const int ntiles = (N + TM - 1) / TM;
    const int gemm_grid = (ntiles < 296) ? ntiles : 296;   // 2 CTAs x 148 SMs
    const int agg_grid  = (NN * 32 + 255) / 256;
    const int nb = (M8 + 1023) / 1024;
    const size_t n4 = (size_t)N * DD / 4;

    detect_k<<<1, 256>>>(et, E);
    zero_cnt_k<<<(M8 + 255) / 256, 256>>>(cnt);
    count_k<<<(E + 255) / 256, 256>>>(ei, et, cnt, E);
    scan1_k<<<nb, 256>>>(cnt, off, bsum, M8);
    scan2_k<<<1, 1024>>>(bsum, nb);
    scan3_k<<<(M8 + 255) / 256, 256>>>(off, cur, bsum, M8);
    scatter_k<<<(E + 255) / 256, 256>>>(ei, et, cur, pack, E);

    cvt16_k<<<(int)((n4 + 255) / 256), 256>>>(x, x16, n4);
    cvtw18_k<<<(18 * DD * DD + 255) / 256, 256>>>(root1, W1, root2, W2, w16);

    // Layer 1: h16 = relu( x@root1 + b1 + sum_r xbar_r@W1r )
    aggx_k<<<agg_grid, 256>>>(off, pack, x16, xbar, E);
    gemmK_k<<<gemm_grid, NTHR, GSMEM>>>(x16, xbar, w16, b1, nullptr, h16, N, ntiles);

    // Layer 2: out = h@root2 + b2 + sum_r hbar_r@W2r
    aggx_k<<<agg_grid, 256>>>(off, pack, h16, xbar, E);
    gemmK_k<<<gemm_grid, NTHR, GSMEM>>>(h16, xbar, w16 + (size_t)9 * DD * DD,
                                        b2, out, nullptr, N, ntiles);
}